// round 2
// baseline (speedup 1.0000x reference)
#include <cuda_runtime.h>
#include <math.h>

#define Bn 32
#define Nn 262144
#define Gn 256
#define CHUNK 16384
#define NBLK ((Bn * Nn) / CHUNK)   // 512
#define BLKPB (Nn / CHUNK)         // 16 blocks per batch

// ---------------- scratch (device globals; no allocation) ----------------
__device__ unsigned g_minkey[Bn * Gn];
__device__ unsigned g_maxkey[Bn * Gn];
__device__ unsigned g_cnt[NBLK][Gn];   // per-block counts -> per-block exclusive prefix (within batch)
__device__ unsigned g_base[Bn][Gn];    // group base offset within batch
__device__ unsigned g_tot[Bn][Gn];     // group totals
__device__ float    g_sorted[Bn * Nn]; // stable-partitioned pr values (n-order within group)
__device__ float4   g_P[Bn * Gn];      // per-group (mn', rng, df, f0')

// Monotone order-preserving float<->uint mapping.
__device__ __forceinline__ unsigned fenc(float f) {
    unsigned u = __float_as_uint(f);
    return (u & 0x80000000u) ? ~u : (u | 0x80000000u);
}
__device__ __forceinline__ float fdec(unsigned u) {
    return __uint_as_float((u & 0x80000000u) ? (u & 0x7fffffffu) : ~u);
}
__device__ __forceinline__ bool bit_isnan(float f) {
    return (__float_as_uint(f) << 1) > 0xFF000000u;
}
__device__ __forceinline__ bool bit_iszero(float f) {
    return (__float_as_uint(f) << 1) == 0u;
}
__device__ __forceinline__ bool bit_nonfinite(float f) {
    return (__float_as_uint(f) << 1) >= 0xFF000000u;
}

// ---------------- kernel 0: init min/max keys ----------------------------
__global__ void k_init() {
    int i = blockIdx.x * blockDim.x + threadIdx.x;
    if (i < Bn * Gn) {
        g_minkey[i] = 0xFFFFFFFFu;
        g_maxkey[i] = 0u;
    }
}

// ---------------- kernel 1: histogram + exact min/max --------------------
__global__ __launch_bounds__(256) void k_hist(const float* __restrict__ pr,
                                              const int* __restrict__ vr) {
    __shared__ unsigned s_min[Gn];
    __shared__ unsigned s_max[Gn];
    __shared__ unsigned s_cnt[Gn];

    int t = threadIdx.x;
    s_min[t] = 0xFFFFFFFFu; s_max[t] = 0u; s_cnt[t] = 0u;
    __syncthreads();

    long base = (long)blockIdx.x * CHUNK;
    int b = blockIdx.x / BLKPB;
    const float4* p4 = (const float4*)(pr + base);
    const int4*   v4 = (const int4*)(vr + base);

    volatile unsigned* vmin = s_min;
    volatile unsigned* vmax = s_max;

#pragma unroll 4
    for (int it = 0; it < CHUNK / 1024; ++it) {
        float4 p = p4[it * 256 + t];
        int4   v = v4[it * 256 + t];
        float pv[4] = {p.x, p.y, p.z, p.w};
        int   gv[4] = {v.x, v.y, v.z, v.w};
#pragma unroll
        for (int e = 0; e < 4; ++e) {
            int g = gv[e];
            unsigned key = fenc(pv[e]);
            atomicAdd(&s_cnt[g], 1u);
            if (key < vmin[g]) atomicMin(&s_min[g], key);
            if (key > vmax[g]) atomicMax(&s_max[g], key);
        }
    }
    __syncthreads();

    g_cnt[blockIdx.x][t] = s_cnt[t];
    if (s_min[t] != 0xFFFFFFFFu) {
        int o = b * Gn + t;
        atomicMin(&g_minkey[o], s_min[t]);
        atomicMax(&g_maxkey[o], s_max[t]);
    }
}

// ---------------- kernel 2: scans (per-batch) ----------------------------
__global__ __launch_bounds__(Gn) void k_scan() {
    int b = blockIdx.x;
    int g = threadIdx.x;

    unsigned run = 0;
#pragma unroll
    for (int blk = 0; blk < BLKPB; ++blk) {
        int idx = b * BLKPB + blk;
        unsigned c = g_cnt[idx][g];
        g_cnt[idx][g] = run;          // exclusive prefix within batch
        run += c;
    }
    g_tot[b][g] = run;

    __shared__ unsigned s[Gn];
    s[g] = run;
    __syncthreads();
    for (int d = 1; d < Gn; d <<= 1) {
        unsigned x = (g >= d) ? s[g - d] : 0u;
        __syncthreads();
        s[g] += x;
        __syncthreads();
    }
    g_base[b][g] = s[g] - run;        // exclusive scan over groups
}

// ---------------- kernel 3: stable scatter (counting sort by group) ------
__global__ __launch_bounds__(256) void k_scatter(const float* __restrict__ pr,
                                                 const int* __restrict__ vr) {
    __shared__ unsigned s_run[Gn];
    __shared__ unsigned s_wh[8][Gn];

    int t = threadIdx.x;
    int w = t >> 5;
    unsigned lt_mask = (1u << (t & 31)) - 1u;
    int b = blockIdx.x / BLKPB;
    long cbase = (long)blockIdx.x * CHUNK;

    s_run[t] = g_base[b][t] + g_cnt[blockIdx.x][t];
    float* dst = g_sorted + (long)b * Nn;

#pragma unroll 1
    for (int tile = 0; tile < CHUNK / 256; ++tile) {
        long n = cbase + tile * 256 + t;
        int   g = vr[n];
        float p = pr[n];

#pragma unroll
        for (int w2 = 0; w2 < 8; ++w2) s_wh[w2][t] = 0u;
        __syncthreads();

        unsigned mask = __match_any_sync(0xFFFFFFFFu, g);
        unsigned lr = __popc(mask & lt_mask);
        if (lr == 0) s_wh[w][g] = __popc(mask);
        __syncthreads();

        unsigned off = s_run[g] + lr;
        for (int w2 = 0; w2 < w; ++w2) off += s_wh[w2][g];
        dst[off] = p;
        __syncthreads();

        unsigned tot = 0;
#pragma unroll
        for (int w2 = 0; w2 < 8; ++w2) tot += s_wh[w2][t];
        s_run[t] += tot;
        __syncthreads();
    }
}

// ---------------- kernel 4: sequential fold + sort + params --------------
__global__ __launch_bounds__(Gn) void k_params(const float* __restrict__ inp_means,
                                               const float* __restrict__ W) {
    __shared__ float skey[Gn];
    __shared__ int   sid[Gn];
    __shared__ float f0u[Gn];
    __shared__ float f1u[Gn];

    int b = blockIdx.x;
    int g = threadIdx.x;
    int o = b * Gn + g;

    // --- exact sequential fp32 fold over the group's elements in n-order ---
    unsigned cnt  = g_tot[b][g];
    unsigned base = g_base[b][g];
    const float* __restrict__ src = g_sorted + (long)b * Nn + base;
    float acc = 0.0f;
    unsigned i = 0;
#pragma unroll 4
    for (; i + 4 <= cnt; i += 4) {
        acc = __fadd_rn(acc, src[i]);
        acc = __fadd_rn(acc, src[i + 1]);
        acc = __fadd_rn(acc, src[i + 2]);
        acc = __fadd_rn(acc, src[i + 3]);
    }
    for (; i < cnt; ++i) acc = __fadd_rn(acc, src[i]);

    bool any = (cnt > 0);
    float vsum = any ? acc : 0.0f;

    float W0 = W[0], W1 = W[1];
    float vmean = __fdiv_rn(__fadd_rn(__fmul_rn(inp_means[o], W0),
                                      __fmul_rn(vsum, W1)),
                            __fadd_rn(W0, W1));

    skey[g] = vmean;
    sid[g]  = g;
    __syncthreads();

    // bitonic sort on (value, id) == jax stable argsort
    for (int k = 2; k <= Gn; k <<= 1) {
        for (int j = k >> 1; j > 0; j >>= 1) {
            int ixj = g ^ j;
            if (ixj > g) {
                float a = skey[g], c = skey[ixj];
                int ia = sid[g], ic = sid[ixj];
                bool up = ((g & k) == 0);
                bool gt = (a > c) || (a == c && ia > ic);
                if (gt == up) {
                    skey[g] = c; skey[ixj] = a;
                    sid[g] = ic; sid[ixj] = ia;
                }
            }
            __syncthreads();
        }
    }

    float vsr   = skey[g];
    float vprev = (g == 0)      ? vsr : skey[g - 1];
    float vnext = (g == Gn - 1) ? __fmul_rn(vsr, 2.0f) : skey[g + 1];
    float f0 = __fdiv_rn(__fadd_rn(vprev, vsr), 1.999f);
    float f1 = __fdiv_rn(__fadd_rn(vsr, vnext), 2.001f);
    f0u[sid[g]] = f0;
    f1u[sid[g]] = f1;
    __syncthreads();

    unsigned mnk = g_minkey[o];
    unsigned mxk = g_maxkey[o];
    float mn = fdec(mnk), mx = fdec(mxk);
    bool ns = (mn == mx);   // empty group -> NaN cmp -> false (ref: inf != -inf)

    float mn2, mx2, f02, f12;
    if (!any) { mn2 = 0.0f; mx2 = 1.0f; f02 = 0.0f; f12 = 0.0f; }
    else {
        mn2 = ns ? 0.0f : mn;
        mx2 = ns ? 1.0f : mx;
        f02 = ns ? 0.0f : f0u[g];
        f12 = ns ? 1.0f : f1u[g];
    }
    float rng = __fsub_rn(mx2, mn2);
    float df  = __fsub_rn(f12, f02);
    g_P[o] = make_float4(mn2, rng, df, f02);
}

// ---------------- kernel 5: elementwise apply (exact op sequence) --------
__device__ __forceinline__ float apply_one(float p, float4 P) {
    float t1  = __fsub_rn(p, P.x);
    float t2  = __fdiv_rn(t1, P.y);
    float t3  = __fmul_rn(t2, P.z);
    float tmp = __fadd_rn(t3, P.w);
    bool bad = bit_isnan(tmp) || bit_iszero(tmp);
    float s = __fdiv_rn(p, bad ? 1.0f : tmp);
    float scale = (bad || bit_nonfinite(s)) ? 0.0f : s;
    return __fmul_rn(p, scale);
}

__global__ __launch_bounds__(256) void k_apply(const float* __restrict__ pr,
                                               const int* __restrict__ vr,
                                               float* __restrict__ out) {
    long base = (long)blockIdx.x * CHUNK;
    int b = blockIdx.x / BLKPB;
    const float4* __restrict__ P = g_P + b * Gn;

    int t = threadIdx.x;
    const float4* p4 = (const float4*)(pr + base);
    const int4*   v4 = (const int4*)(vr + base);
    float4*       o4 = (float4*)(out + base);

#pragma unroll 4
    for (int it = 0; it < CHUNK / 1024; ++it) {
        float4 p = p4[it * 256 + t];
        int4   v = v4[it * 256 + t];
        float4 r;
        r.x = apply_one(p.x, __ldg(&P[v.x]));
        r.y = apply_one(p.y, __ldg(&P[v.y]));
        r.z = apply_one(p.z, __ldg(&P[v.z]));
        r.w = apply_one(p.w, __ldg(&P[v.w]));
        o4[it * 256 + t] = r;
    }
}

// ---------------- launch --------------------------------------------------
extern "C" void kernel_launch(void* const* d_in, const int* in_sizes, int n_in,
                              void* d_out, int out_size) {
    const float* pr        = (const float*)d_in[0];
    const float* inp_means = (const float*)d_in[1];
    const int*   vr        = (const int*)d_in[2];
    const float* W         = (const float*)d_in[3];
    float* out = (float*)d_out;

    k_init<<<(Bn * Gn + 255) / 256, 256>>>();
    k_hist<<<NBLK, 256>>>(pr, vr);
    k_scan<<<Bn, Gn>>>();
    k_scatter<<<NBLK, 256>>>(pr, vr);
    k_params<<<Bn, Gn>>>(inp_means, W);
    k_apply<<<NBLK, 256>>>(pr, vr, out);
}